// round 1
// baseline (speedup 1.0000x reference)
#include <cuda_runtime.h>

#define N_NODES 50000
#define D 128

// ---------------- device scratch (no allocation allowed) ----------------
__device__ float g_agg[(size_t)N_NODES * D];   // h = x + neighbor-sum
__device__ float g_y[(size_t)N_NODES * D];     // layer activations
__device__ int   g_is64;                       // edge_index dtype flag

// ---------------- dtype detection for edge_index ----------------
// If the buffer is int64, every entry is in [0, N_NODES). If it is int32,
// reading it as int64 fuses two indices -> values >= 2^32 with overwhelming
// probability across 32 samples.
__global__ void detect_kernel(const void* __restrict__ ei) {
    if (blockIdx.x == 0 && threadIdx.x == 0) {
        const long long* p = (const long long*)ei;
        int ok = 1;
        #pragma unroll
        for (int i = 0; i < 32; i++) {
            long long v = p[i];
            if (v < 0 || v >= N_NODES) { ok = 0; }
        }
        g_is64 = ok;
    }
}

// ---------------- agg = x (vectorized copy) ----------------
__global__ void copy_kernel(const float4* __restrict__ src, float4* __restrict__ dst, int n4) {
    int i = blockIdx.x * blockDim.x + threadIdx.x;
    if (i < n4) dst[i] = src[i];
}

// ---------------- edge scatter: agg[dst] += x[src] ----------------
// One warp per edge; lane l handles floats [4l, 4l+4) of the 128-wide row.
// Vector atomic (red.global.add.v4.f32) -> 32 atomics per edge instead of 128.
__global__ void scatter_kernel(const float* __restrict__ x,
                               float* __restrict__ agg,
                               const void* __restrict__ ei,
                               int E) {
    int gw   = (blockIdx.x * blockDim.x + threadIdx.x) >> 5;
    int lane = threadIdx.x & 31;
    if (gw >= E) return;

    long long s, d;
    if (g_is64) {
        const long long* p = (const long long*)ei;
        s = __ldg(p + gw);
        d = __ldg(p + E + gw);
    } else {
        const int* p = (const int*)ei;
        s = __ldg(p + gw);
        d = __ldg(p + E + gw);
    }

    float4 v = __ldg((const float4*)(x + (size_t)s * D) + lane);
    float* a = agg + (size_t)d * D + lane * 4;
    asm volatile("red.global.add.v4.f32 [%0], {%1, %2, %3, %4};"
                 :: "l"(a), "f"(v.x), "f"(v.y), "f"(v.z), "f"(v.w)
                 : "memory");
}

// ---------------- SGEMM: out = act(A @ W + b) ----------------
// A: [N, 128]  W: [128, C]  b: [C]  out: [N, C]
// BM=64 rows/block, BK=32 k-chunk, 256 threads, thread tile = 4 rows x (C/16) cols.
template <int C, bool RELU>
__global__ __launch_bounds__(256)
void gemm_kernel(const float* __restrict__ A,
                 const float* __restrict__ W,
                 const float* __restrict__ bias,
                 float* __restrict__ out,
                 int N) {
    constexpr int BM  = 64;
    constexpr int BK  = 32;
    constexpr int CPT = C / 16;                 // cols per thread (8 or 4)

    __shared__ __align__(16) float As[BM * (BK + 1)];   // +1 pad: kill bank conflicts
    __shared__ __align__(16) float Ws[BK * C];

    const int tid  = threadIdx.x;
    const int tx   = tid & 15;                  // 16 col groups
    const int ty   = tid >> 4;                  // 16 row groups (x4 rows)
    const int row0 = blockIdx.x * BM;

    float acc[4][CPT];
    #pragma unroll
    for (int i = 0; i < 4; i++)
        #pragma unroll
        for (int j = 0; j < CPT; j++) acc[i][j] = 0.0f;

    for (int kb = 0; kb < D; kb += BK) {
        // stage A chunk: 64x32 floats = 512 float4, 2 per thread
        #pragma unroll
        for (int t = tid; t < BM * BK / 4; t += 256) {
            int r  = t >> 3;            // /(BK/4)
            int c4 = t & 7;
            float4 v = make_float4(0.f, 0.f, 0.f, 0.f);
            if (row0 + r < N)
                v = __ldg((const float4*)(A + (size_t)(row0 + r) * D + kb) + c4);
            float* dst = &As[r * (BK + 1) + c4 * 4];
            dst[0] = v.x; dst[1] = v.y; dst[2] = v.z; dst[3] = v.w;
        }
        // stage W chunk: 32xC floats
        #pragma unroll
        for (int t = tid; t < BK * C / 4; t += 256)
            ((float4*)Ws)[t] = __ldg((const float4*)(W + (size_t)kb * C) + t);
        __syncthreads();

        #pragma unroll
        for (int k = 0; k < BK; k++) {
            float a[4];
            #pragma unroll
            for (int i = 0; i < 4; i++)
                a[i] = As[(ty * 4 + i) * (BK + 1) + k];
            float w[CPT];
            #pragma unroll
            for (int j = 0; j < CPT; j += 4) {
                float4 wv = *(const float4*)&Ws[k * C + tx * CPT + j];
                w[j] = wv.x; w[j + 1] = wv.y; w[j + 2] = wv.z; w[j + 3] = wv.w;
            }
            #pragma unroll
            for (int i = 0; i < 4; i++)
                #pragma unroll
                for (int j = 0; j < CPT; j++)
                    acc[i][j] = fmaf(a[i], w[j], acc[i][j]);
        }
        __syncthreads();
    }

    // epilogue: bias (+ ReLU), vectorized stores
    #pragma unroll
    for (int i = 0; i < 4; i++) {
        int r = row0 + ty * 4 + i;
        if (r >= N) continue;
        #pragma unroll
        for (int j = 0; j < CPT; j += 4) {
            float4 b4 = __ldg((const float4*)(bias + tx * CPT + j));
            float4 v;
            v.x = acc[i][j + 0] + b4.x;
            v.y = acc[i][j + 1] + b4.y;
            v.z = acc[i][j + 2] + b4.z;
            v.w = acc[i][j + 3] + b4.w;
            if (RELU) {
                v.x = fmaxf(v.x, 0.f); v.y = fmaxf(v.y, 0.f);
                v.z = fmaxf(v.z, 0.f); v.w = fmaxf(v.w, 0.f);
            }
            *(float4*)(out + (size_t)r * C + tx * CPT + j) = v;
        }
    }
}

// ---------------- in-place log_softmax over 64 cols, warp per row ----------------
__global__ void lsm_kernel(float* __restrict__ y, int N) {
    int row  = (blockIdx.x * blockDim.x + threadIdx.x) >> 5;
    int lane = threadIdx.x & 31;
    if (row >= N) return;
    float* p = y + (size_t)row * 64;
    float v0 = p[lane], v1 = p[lane + 32];
    float m = fmaxf(v0, v1);
    #pragma unroll
    for (int o = 16; o; o >>= 1) m = fmaxf(m, __shfl_xor_sync(0xFFFFFFFFu, m, o));
    float s = expf(v0 - m) + expf(v1 - m);
    #pragma unroll
    for (int o = 16; o; o >>= 1) s += __shfl_xor_sync(0xFFFFFFFFu, s, o);
    float l = m + logf(s);
    p[lane]      = v0 - l;
    p[lane + 32] = v1 - l;
}

// ---------------- launch ----------------
extern "C" void kernel_launch(void* const* d_in, const int* in_sizes, int n_in,
                              void* d_out, int out_size) {
    const float* feature = (const float*)d_in[0];
    const void*  ei      = d_in[1];
    const float* W1      = (const float*)d_in[2];
    const float* b1      = (const float*)d_in[3];
    const float* Wh      = (const float*)d_in[4];
    const float* bh      = (const float*)d_in[5];
    const float* Wo      = (const float*)d_in[6];
    const float* bo      = (const float*)d_in[7];
    float* out = (float*)d_out;

    const int N = N_NODES;
    const int E = in_sizes[1] / 2;          // element count is dtype-independent

    float *agg, *y;
    cudaGetSymbolAddress((void**)&agg, g_agg);
    cudaGetSymbolAddress((void**)&y,   g_y);

    const int n4      = N * D / 4;                    // 1.6M float4
    const int cpB     = (n4 + 255) / 256;             // copy blocks
    const int scB     = (E * 32 + 255) / 256;         // scatter blocks (warp/edge)
    const int gmB     = (N + 63) / 64;                // gemm blocks
    const int lsB     = (N * 32 + 255) / 256;         // logsoftmax blocks

    detect_kernel<<<1, 1>>>(ei);

    // ---- layer 1: h = feature + agg(feature); y = relu(h@W1 + b1)
    copy_kernel<<<cpB, 256>>>((const float4*)feature, (float4*)agg, n4);
    scatter_kernel<<<scB, 256>>>(feature, agg, ei, E);
    gemm_kernel<128, true><<<gmB, 256>>>(agg, W1, b1, y, N);

    // ---- layer 2
    copy_kernel<<<cpB, 256>>>((const float4*)y, (float4*)agg, n4);
    scatter_kernel<<<scB, 256>>>(y, agg, ei, E);
    gemm_kernel<128, true><<<gmB, 256>>>(agg, Wh, bh, y, N);

    // ---- layer 3 + log_softmax (in place on d_out)
    copy_kernel<<<cpB, 256>>>((const float4*)y, (float4*)agg, n4);
    scatter_kernel<<<scB, 256>>>(y, agg, ei, E);
    gemm_kernel<64, false><<<gmB, 256>>>(agg, Wo, bo, out, N);
    lsm_kernel<<<lsB, 256>>>(out, N);
}

// round 2
// speedup vs baseline: 2.6181x; 2.6181x over previous
#include <cuda_runtime.h>

#define N_NODES 50000
#define D 128
#define E_MAX 800000

// ---------------- device scratch (no allocation allowed) ----------------
__device__ float g_agg[(size_t)N_NODES * D];   // h = x + neighbor-sum
__device__ float g_y[(size_t)N_NODES * D];     // layer activations
__device__ int   g_is64;                       // edge_index dtype flag
__device__ int   g_src[E_MAX];
__device__ int   g_dst[E_MAX];
__device__ int   g_perm[E_MAX];                // CSR: neighbor src ids grouped by dst
__device__ int   g_deg[N_NODES];
__device__ int   g_off[N_NODES];
__device__ int   g_cur[N_NODES];
__device__ int   g_bsum[256];

// ---------------- f32x2 packed-math helpers (SASS FFMA2 path) ----------------
__device__ __forceinline__ unsigned long long pack2(float a, float b) {
    unsigned long long r;
    asm("mov.b64 %0, {%1, %2};" : "=l"(r) : "f"(a), "f"(b));
    return r;
}
__device__ __forceinline__ void fma2(unsigned long long& d, unsigned long long a,
                                     unsigned long long b) {
    asm("fma.rn.f32x2 %0, %1, %2, %0;" : "+l"(d) : "l"(a), "l"(b));
}
__device__ __forceinline__ float2 unpack2(unsigned long long v) {
    float2 r;
    asm("mov.b64 {%0, %1}, %2;" : "=f"(r.x), "=f"(r.y) : "l"(v));
    return r;
}

// ---------------- dtype detection for edge_index ----------------
__global__ void detect_kernel(const void* __restrict__ ei) {
    if (blockIdx.x == 0 && threadIdx.x == 0) {
        const long long* p = (const long long*)ei;
        int ok = 1;
        #pragma unroll
        for (int i = 0; i < 32; i++) {
            long long v = p[i];
            if (v < 0 || v >= N_NODES) ok = 0;
        }
        g_is64 = ok;
    }
}

// ---------------- CSR build ----------------
__global__ void zero_deg_kernel() {
    int i = blockIdx.x * blockDim.x + threadIdx.x;
    if (i < N_NODES) g_deg[i] = 0;
}

// convert edge index to int32 + histogram of dst degrees
__global__ void convert_kernel(const void* __restrict__ ei, int E) {
    int i = blockIdx.x * blockDim.x + threadIdx.x;
    if (i >= E) return;
    int s, d;
    if (g_is64) {
        const long long* p = (const long long*)ei;
        s = (int)__ldg(p + i);
        d = (int)__ldg(p + E + i);
    } else {
        const int* p = (const int*)ei;
        s = __ldg(p + i);
        d = __ldg(p + E + i);
    }
    g_src[i] = s;
    g_dst[i] = d;
    atomicAdd(&g_deg[d], 1);
}

// per-256-block exclusive scan of deg -> off, block totals to bsum
__global__ void scanA_kernel(int n) {
    __shared__ int sh[8];
    int t = threadIdx.x, i = blockIdx.x * 256 + t;
    int v = (i < n) ? g_deg[i] : 0;
    int lane = t & 31, w = t >> 5;
    int x = v;
    #pragma unroll
    for (int o = 1; o < 32; o <<= 1) {
        int y = __shfl_up_sync(0xFFFFFFFFu, x, o);
        if (lane >= o) x += y;
    }
    if (lane == 31) sh[w] = x;
    __syncthreads();
    if (t < 8) {
        int s = sh[t];
        #pragma unroll
        for (int o = 1; o < 8; o <<= 1) {
            int y = __shfl_up_sync(0xFFu, s, o);
            if (t >= o) s += y;
        }
        sh[t] = s;
    }
    __syncthreads();
    int incl = x + (w ? sh[w - 1] : 0);
    if (i < n) g_off[i] = incl - v;
    if (t == 255) g_bsum[blockIdx.x] = incl;
}

// single-block exclusive scan of block sums (nb <= 256)
__global__ void scanB_kernel(int nb) {
    __shared__ int sh[8];
    int t = threadIdx.x;
    int v = (t < nb) ? g_bsum[t] : 0;
    int lane = t & 31, w = t >> 5;
    int x = v;
    #pragma unroll
    for (int o = 1; o < 32; o <<= 1) {
        int y = __shfl_up_sync(0xFFFFFFFFu, x, o);
        if (lane >= o) x += y;
    }
    if (lane == 31) sh[w] = x;
    __syncthreads();
    if (t < 8) {
        int s = sh[t];
        #pragma unroll
        for (int o = 1; o < 8; o <<= 1) {
            int y = __shfl_up_sync(0xFFu, s, o);
            if (t >= o) s += y;
        }
        sh[t] = s;
    }
    __syncthreads();
    int incl = x + (w ? sh[w - 1] : 0);
    if (t < nb) g_bsum[t] = incl - v;
}

__global__ void scanC_kernel(int n) {
    int i = blockIdx.x * blockDim.x + threadIdx.x;
    if (i >= n) return;
    int o = g_off[i] + g_bsum[i >> 8];
    g_off[i] = o;
    g_cur[i] = o;
}

__global__ void fill_kernel(int E) {
    int i = blockIdx.x * blockDim.x + threadIdx.x;
    if (i >= E) return;
    int d = g_dst[i];
    int p = atomicAdd(&g_cur[d], 1);
    g_perm[p] = g_src[i];
}

// ---------------- gather aggregation: agg[i] = x[i] + sum_{j in N(i)} x[j] ----
// One warp per node; lane holds float4 (cols 4l..4l+4). No atomics, no copies.
__global__ void gather_kernel(const float* __restrict__ x, float* __restrict__ agg, int N) {
    int node = (blockIdx.x * blockDim.x + threadIdx.x) >> 5;
    int lane = threadIdx.x & 31;
    if (node >= N) return;
    const float4* x4 = (const float4*)x;
    int off = g_off[node];
    int deg = g_deg[node];
    float4 acc = __ldg(x4 + (size_t)node * 32 + lane);   // (1+eps)*x, eps=0
    for (int j0 = 0; j0 < deg; j0 += 32) {
        int idx = (j0 + lane < deg) ? g_perm[off + j0 + lane] : 0;
        int cnt = min(32, deg - j0);
        for (int t = 0; t < cnt; t++) {
            int s = __shfl_sync(0xFFFFFFFFu, idx, t);
            float4 v = __ldg(x4 + (size_t)s * 32 + lane);
            acc.x += v.x; acc.y += v.y; acc.z += v.z; acc.w += v.w;
        }
    }
    ((float4*)agg)[(size_t)node * 32 + lane] = acc;
}

// ---------------- SGEMM: out = act(A @ W + b), packed f32x2 FMA ----------------
// A: [N, 128]  W: [128, C]  BM=128, BN=C, BK=32, 256 threads.
// micro-tile: RPT rows x 8 cols per thread (RPT = 8 for C=128, 4 for C=64).
template <int C, bool RELU>
__global__ __launch_bounds__(256, 2)
void gemm_kernel(const float* __restrict__ A,
                 const float* __restrict__ W,
                 const float* __restrict__ bias,
                 float* __restrict__ out,
                 int N) {
    constexpr int BM  = 128;
    constexpr int BK  = 32;
    constexpr int NCG = C / 8;        // col groups (16 or 8)
    constexpr int NRG = 256 / NCG;    // row groups (16 or 32)
    constexpr int RPT = BM / NRG;     // rows per thread (8 or 4)

    __shared__ __align__(16) float As[BK][BM];   // transposed: As[k][m]
    __shared__ __align__(16) float Ws[BK][C];

    const int tid  = threadIdx.x;
    const int tx   = tid % NCG;
    const int ty   = tid / NCG;
    const int row0 = blockIdx.x * BM;

    unsigned long long acc[RPT][4];   // 4 f32x2 pairs = 8 cols
    #pragma unroll
    for (int i = 0; i < RPT; i++)
        #pragma unroll
        for (int j = 0; j < 4; j++) acc[i][j] = 0ULL;

    for (int kb = 0; kb < D; kb += BK) {
        // stage A transposed: 1024 float4 over 256 threads (r fastest -> no ST conflicts)
        #pragma unroll
        for (int t = tid; t < BM * BK / 4; t += 256) {
            int r = t & 127, c4 = t >> 7;
            float4 v = make_float4(0.f, 0.f, 0.f, 0.f);
            if (row0 + r < N)
                v = __ldg((const float4*)(A + (size_t)(row0 + r) * D + kb) + c4);
            As[c4 * 4 + 0][r] = v.x;
            As[c4 * 4 + 1][r] = v.y;
            As[c4 * 4 + 2][r] = v.z;
            As[c4 * 4 + 3][r] = v.w;
        }
        // stage W chunk (contiguous BK*C floats)
        #pragma unroll
        for (int t = tid; t < BK * C / 4; t += 256)
            ((float4*)Ws)[t] = __ldg((const float4*)(W + (size_t)kb * C) + t);
        __syncthreads();

        #pragma unroll
        for (int k = 0; k < BK; k++) {
            // a values: contiguous rows in As[k], vector loads
            float av[RPT];
            {
                const float4* ap = (const float4*)&As[k][ty * RPT];
                float4 a0 = ap[0];
                av[0] = a0.x; av[1] = a0.y; av[2] = a0.z; av[3] = a0.w;
                if (RPT == 8) {
                    float4 a1 = ap[1];
                    av[4] = a1.x; av[5] = a1.y; av[6] = a1.z; av[7] = a1.w;
                }
            }
            unsigned long long adup[RPT];
            #pragma unroll
            for (int i = 0; i < RPT; i++) adup[i] = pack2(av[i], av[i]);

            const unsigned long long* wrow = (const unsigned long long*)&Ws[k][tx * 8];
            unsigned long long w2[4];
            #pragma unroll
            for (int j = 0; j < 4; j++) w2[j] = wrow[j];

            #pragma unroll
            for (int i = 0; i < RPT; i++)
                #pragma unroll
                for (int j = 0; j < 4; j++)
                    fma2(acc[i][j], adup[i], w2[j]);
        }
        __syncthreads();
    }

    // epilogue: bias (+ReLU), float4 stores
    float4 b0 = __ldg((const float4*)(bias + tx * 8));
    float4 b1 = __ldg((const float4*)(bias + tx * 8) + 1);
    #pragma unroll
    for (int i = 0; i < RPT; i++) {
        int r = row0 + ty * RPT + i;
        if (r >= N) continue;
        float2 p0 = unpack2(acc[i][0]);
        float2 p1 = unpack2(acc[i][1]);
        float2 p2 = unpack2(acc[i][2]);
        float2 p3 = unpack2(acc[i][3]);
        float4 v0 = make_float4(p0.x + b0.x, p0.y + b0.y, p1.x + b0.z, p1.y + b0.w);
        float4 v1 = make_float4(p2.x + b1.x, p2.y + b1.y, p3.x + b1.z, p3.y + b1.w);
        if (RELU) {
            v0.x = fmaxf(v0.x, 0.f); v0.y = fmaxf(v0.y, 0.f);
            v0.z = fmaxf(v0.z, 0.f); v0.w = fmaxf(v0.w, 0.f);
            v1.x = fmaxf(v1.x, 0.f); v1.y = fmaxf(v1.y, 0.f);
            v1.z = fmaxf(v1.z, 0.f); v1.w = fmaxf(v1.w, 0.f);
        }
        float* o = out + (size_t)r * C + tx * 8;
        *(float4*)o = v0;
        *((float4*)o + 1) = v1;
    }
}

// ---------------- in-place log_softmax over 64 cols, warp per row ----------------
__global__ void lsm_kernel(float* __restrict__ y, int N) {
    int row  = (blockIdx.x * blockDim.x + threadIdx.x) >> 5;
    int lane = threadIdx.x & 31;
    if (row >= N) return;
    float* p = y + (size_t)row * 64;
    float v0 = p[lane], v1 = p[lane + 32];
    float m = fmaxf(v0, v1);
    #pragma unroll
    for (int o = 16; o; o >>= 1) m = fmaxf(m, __shfl_xor_sync(0xFFFFFFFFu, m, o));
    float s = expf(v0 - m) + expf(v1 - m);
    #pragma unroll
    for (int o = 16; o; o >>= 1) s += __shfl_xor_sync(0xFFFFFFFFu, s, o);
    float l = m + logf(s);
    p[lane]      = v0 - l;
    p[lane + 32] = v1 - l;
}

// ---------------- launch ----------------
extern "C" void kernel_launch(void* const* d_in, const int* in_sizes, int n_in,
                              void* d_out, int out_size) {
    const float* feature = (const float*)d_in[0];
    const void*  ei      = d_in[1];
    const float* W1      = (const float*)d_in[2];
    const float* b1      = (const float*)d_in[3];
    const float* Wh      = (const float*)d_in[4];
    const float* bh      = (const float*)d_in[5];
    const float* Wo      = (const float*)d_in[6];
    const float* bo      = (const float*)d_in[7];
    float* out = (float*)d_out;

    const int N = N_NODES;
    int E = in_sizes[1] / 2;
    if (E > E_MAX) E = E_MAX;

    float *agg, *y;
    cudaGetSymbolAddress((void**)&agg, g_agg);
    cudaGetSymbolAddress((void**)&y,   g_y);

    const int nB   = (N + 255) / 256;
    const int eB   = (E + 255) / 256;
    const int saB  = (N + 255) / 256;           // scanA blocks (196)
    const int gaB  = (N * 32 + 255) / 256;      // gather blocks (warp/node)
    const int gmB  = (N + 127) / 128;           // gemm blocks (391)
    const int lsB  = (N * 32 + 255) / 256;

    // ---- CSR build (once; reused by all 3 layers)
    detect_kernel<<<1, 1>>>(ei);
    zero_deg_kernel<<<nB, 256>>>();
    convert_kernel<<<eB, 256>>>(ei, E);
    scanA_kernel<<<saB, 256>>>(N);
    scanB_kernel<<<1, 256>>>(saB);
    scanC_kernel<<<nB, 256>>>(N);
    fill_kernel<<<eB, 256>>>(E);

    // ---- layer 1
    gather_kernel<<<gaB, 256>>>(feature, agg, N);
    gemm_kernel<128, true><<<gmB, 256>>>(agg, W1, b1, y, N);

    // ---- layer 2
    gather_kernel<<<gaB, 256>>>(y, agg, N);
    gemm_kernel<128, true><<<gmB, 256>>>(agg, Wh, bh, y, N);

    // ---- layer 3 + log_softmax
    gather_kernel<<<gaB, 256>>>(y, agg, N);
    gemm_kernel<64, false><<<gmB, 256>>>(agg, Wo, bo, out, N);
    lsm_kernel<<<lsB, 256>>>(out, N);
}